// round 1
// baseline (speedup 1.0000x reference)
#include <cuda_runtime.h>
#include <math.h>

// ---------------- problem constants ----------------
#define NPTS   100000
#define NEIGH  16
#define EDGES  (NPTS * NEIGH)
#define DIN    128
#define D2     64
#define DOUT   256
#define KPTS   15
#define SIGMA  0.04f
#define NEG    0.1f
#define EPSBN  1e-5f

// ---------------- scratch (device globals; no runtime alloc) ----------------
__device__ float  g_t  [(size_t)NPTS * D2];          // x@W1 (pre-BN)
__device__ float  g_h  [(size_t)NPTS * D2];          // h after BN+leaky; reused for ybn
__device__ float  g_H  [(size_t)NPTS * KPTS * D2];   // h @ Wbig  (384 MB)
__device__ float  g_y  [(size_t)NPTS * D2];          // KPConv accumulation (atomics)
__device__ float  g_u2 [(size_t)NPTS * DOUT];        // ybn @ W2
__device__ float  g_usc[(size_t)NPTS * DOUT];        // x @ Wsc
__device__ float  g_Wbig[D2 * KPTS * D2];            // [64 x 960] repacked W_kp
__device__ double g_stats[1280];  // t:[0,128) y:[128,256) u2:[256,768) usc:[768,1280)

__device__ __forceinline__ float* get_buf(int which) {
    switch (which) {
        case 0: return g_t;
        case 1: return g_h;
        case 2: return g_H;
        case 3: return g_y;
        case 4: return g_u2;
        case 5: return g_usc;
        default: return g_Wbig;
    }
}

// ---------------- zero accumulators ----------------
__global__ void zero_kernel() {
    size_t i = (size_t)blockIdx.x * blockDim.x + threadIdx.x;
    size_t stride = (size_t)gridDim.x * blockDim.x;
    const size_t ny = (size_t)NPTS * D2;
    for (size_t j = i; j < ny; j += stride) g_y[j] = 0.f;
    if (i < 1280) g_stats[i] = 0.0;
}

// ---------------- repack W_kp [K,D2,D2] -> Wbig [D2, K*D2] ----------------
__global__ void prep_wbig(const float* __restrict__ Wkp) {
    int i = blockIdx.x * blockDim.x + threadIdx.x;
    if (i >= D2 * KPTS * D2) return;
    int c   = i / (KPTS * D2);
    int col = i % (KPTS * D2);
    int k = col >> 6;
    int j = col & 63;
    g_Wbig[i] = Wkp[k * (D2 * D2) + c * D2 + j];
}

// ---------------- fp32 tiled GEMM: C[M,Nc] = A[M,Kd] @ B[Kd,Nc] ----------------
// BM=64, BN=64, BK=32, 256 threads, 4x4 micro-tile
__global__ __launch_bounds__(256) void gemm_kernel(
    const float* __restrict__ Aext, int aWhich,
    const float* __restrict__ Bext, int bWhich,
    int cWhich, int M, int Kd, int Nc)
{
    const float* A = (aWhich < 0) ? Aext : get_buf(aWhich);
    const float* B = (bWhich < 0) ? Bext : get_buf(bWhich);
    float*       C = get_buf(cWhich);

    __shared__ float As[32][68];   // A^T tile (padded, float4-aligned rows)
    __shared__ float Bs[32][64];

    int m0 = blockIdx.x * 64;
    int n0 = blockIdx.y * 64;
    int tid = threadIdx.x;
    int tx = tid & 15;
    int ty = tid >> 4;

    float acc[4][4];
#pragma unroll
    for (int i = 0; i < 4; ++i)
#pragma unroll
        for (int j = 0; j < 4; ++j) acc[i][j] = 0.f;

    for (int k0 = 0; k0 < Kd; k0 += 32) {
#pragma unroll
        for (int i = 0; i < 8; ++i) {          // 64x32 A tile
            int idx = tid + i * 256;
            int r = idx >> 5;
            int c = idx & 31;
            int gr = m0 + r;
            float v = (gr < M) ? A[(size_t)gr * Kd + k0 + c] : 0.f;
            As[c][r] = v;
        }
#pragma unroll
        for (int i = 0; i < 8; ++i) {          // 32x64 B tile
            int idx = tid + i * 256;
            int r = idx >> 6;
            int c = idx & 63;
            Bs[r][c] = B[(size_t)(k0 + r) * Nc + n0 + c];
        }
        __syncthreads();
#pragma unroll
        for (int kk = 0; kk < 32; ++kk) {
            float4 a4 = *(const float4*)&As[kk][ty * 4];
            float4 b4 = *(const float4*)&Bs[kk][tx * 4];
            float av[4] = {a4.x, a4.y, a4.z, a4.w};
            float bv[4] = {b4.x, b4.y, b4.z, b4.w};
#pragma unroll
            for (int i = 0; i < 4; ++i)
#pragma unroll
                for (int j = 0; j < 4; ++j) acc[i][j] += av[i] * bv[j];
        }
        __syncthreads();
    }

#pragma unroll
    for (int i = 0; i < 4; ++i) {
        int row = m0 + ty * 4 + i;
        if (row < M) {
#pragma unroll
            for (int j = 0; j < 4; ++j)
                C[(size_t)row * Nc + n0 + tx * 4 + j] = acc[i][j];
        }
    }
}

// ---------------- per-channel sum / sumsq (fp64) ----------------
template <int C>
__global__ __launch_bounds__(256) void stats_kernel(int inWhich, int M, int statOff) {
    const float* in = get_buf(inWhich);
    const int rowsPerIter = 256 / C;
    int c  = threadIdx.x % C;
    int ro = threadIdx.x / C;
    double s = 0.0, s2 = 0.0;
    for (int r = blockIdx.x * rowsPerIter + ro; r < M; r += gridDim.x * rowsPerIter) {
        float v = in[(size_t)r * C + c];
        s += (double)v;
        s2 += (double)v * (double)v;
    }
    __shared__ double sh[512];
    sh[threadIdx.x] = s;
    sh[256 + threadIdx.x] = s2;
    __syncthreads();
    if (threadIdx.x < C) {
        for (int j = C + threadIdx.x; j < 256; j += C) {
            s += sh[j];
            s2 += sh[256 + j];
        }
        atomicAdd(&g_stats[statOff + c], s);
        atomicAdd(&g_stats[statOff + C + c], s2);
    }
}

// ---------------- BN (+optional leaky) elementwise, C=64 ----------------
__global__ void bn_apply64(int inWhich, int outWhich, int statOff,
                           const float* __restrict__ g, const float* __restrict__ b,
                           int M) {
    const float* in = get_buf(inWhich);
    float* out = get_buf(outWhich);
    int i = blockIdx.x * blockDim.x + threadIdx.x;
    if (i >= M * D2) return;
    int c = i & 63;
    double m = g_stats[statOff + c] / (double)M;
    double v = g_stats[statOff + D2 + c] / (double)M - m * m;
    float rstd = rsqrtf((float)v + EPSBN);
    float scale = g[c] * rstd;
    float shift = b[c] - (float)m * scale;
    float val = in[i] * scale + shift;
    out[i] = (val >= 0.f) ? val : NEG * val;
}

// ---------------- edge kernel: y[q] += sum_k infl(e,k) * Hbig[r, k*64 : ] ----------------
__global__ __launch_bounds__(256) void edge_kernel(
    const float* __restrict__ pos, const int* __restrict__ e_ref,
    const int* __restrict__ e_query, const float* __restrict__ kp, int E)
{
    int lane = threadIdx.x & 31;
    int warp = threadIdx.x >> 5;
    int e = blockIdx.x * 8 + warp;
    if (e >= E) return;

    int r = e_ref[e];
    int q = e_query[e];

    float rx = __ldg(&pos[r * 4 + 1]) - __ldg(&pos[q * 4 + 1]);
    float ry = __ldg(&pos[r * 4 + 2]) - __ldg(&pos[q * 4 + 2]);
    float rz = __ldg(&pos[r * 4 + 3]) - __ldg(&pos[q * 4 + 3]);

    float infl = 0.f;
    if (lane < KPTS) {
        float dx = rx - __ldg(&kp[lane * 3 + 0]);
        float dy = ry - __ldg(&kp[lane * 3 + 1]);
        float dz = rz - __ldg(&kp[lane * 3 + 2]);
        float d2 = dx * dx + dy * dy + dz * dz;
        if (d2 < SIGMA * SIGMA)
            infl = 1.f - sqrtf(d2) * (1.f / SIGMA);
    }
    unsigned nz = __ballot_sync(0xffffffffu, infl > 0.f);
    if (!nz) return;

    const float* Hrow = g_H + (size_t)r * (KPTS * D2);
    float acc0 = 0.f, acc1 = 0.f;
    while (nz) {
        int k = __ffs(nz) - 1;
        nz &= nz - 1;
        float w = __shfl_sync(0xffffffffu, infl, k);
        acc0 += w * __ldg(&Hrow[k * 64 + lane]);
        acc1 += w * __ldg(&Hrow[k * 64 + 32 + lane]);
    }
    atomicAdd(&g_y[(size_t)q * D2 + lane], acc0);
    atomicAdd(&g_y[(size_t)q * D2 + 32 + lane], acc1);
}

// ---------------- final: out = leaky(bn(u2)) + bn(usc) ----------------
__global__ void final_kernel(float* __restrict__ out,
                             const float* __restrict__ g2, const float* __restrict__ b2,
                             const float* __restrict__ gsc, const float* __restrict__ bsc,
                             int M) {
    int i = blockIdx.x * blockDim.x + threadIdx.x;
    if (i >= M * DOUT) return;
    int c = i & 255;

    double m2 = g_stats[256 + c] / (double)M;
    double v2 = g_stats[256 + DOUT + c] / (double)M - m2 * m2;
    float rstd2 = rsqrtf((float)v2 + EPSBN);
    float sc2 = g2[c] * rstd2;
    float sh2 = b2[c] - (float)m2 * sc2;

    double ms = g_stats[768 + c] / (double)M;
    double vs = g_stats[768 + DOUT + c] / (double)M - ms * ms;
    float rstds = rsqrtf((float)vs + EPSBN);
    float scs = gsc[c] * rstds;
    float shs = bsc[c] - (float)ms * scs;

    float a = g_u2[i] * sc2 + sh2;
    a = (a >= 0.f) ? a : NEG * a;
    float s = g_usc[i] * scs + shs;
    out[i] = a + s;
}

// ---------------- launch ----------------
extern "C" void kernel_launch(void* const* d_in, const int* in_sizes, int n_in,
                              void* d_out, int out_size) {
    const float* pos    = (const float*)d_in[0];
    const float* x      = (const float*)d_in[1];
    const int*   e_ref  = (const int*)  d_in[2];
    const int*   e_qry  = (const int*)  d_in[3];
    const float* W1     = (const float*)d_in[4];
    const float* g1     = (const float*)d_in[5];
    const float* b1     = (const float*)d_in[6];
    const float* kp     = (const float*)d_in[7];
    const float* Wkp    = (const float*)d_in[8];
    const float* gkp    = (const float*)d_in[9];
    const float* bkp    = (const float*)d_in[10];
    const float* W2     = (const float*)d_in[11];
    const float* g2     = (const float*)d_in[12];
    const float* b2     = (const float*)d_in[13];
    const float* Wsc    = (const float*)d_in[14];
    const float* gsc    = (const float*)d_in[15];
    const float* bsc    = (const float*)d_in[16];
    float* out = (float*)d_out;

    const int M = NPTS;
    const int E = in_sizes[2];

    // 0. zero y accumulator + stats
    zero_kernel<<<4096, 256>>>();
    // 0b. repack W_kp
    prep_wbig<<<(D2 * KPTS * D2 + 255) / 256, 256>>>(Wkp);

    dim3 gemmGrid1((M + 63) / 64, 1);
    dim3 gemmGridH((M + 63) / 64, (KPTS * D2) / 64);
    dim3 gemmGrid4((M + 63) / 64, DOUT / 64);

    // 1. t = x @ W1
    gemm_kernel<<<gemmGrid1, 256>>>(x, -1, W1, -1, /*C=*/0, M, DIN, D2);
    // 2. stats(t) ; h = leaky(bn(t))
    stats_kernel<64><<<240, 256>>>(0, M, 0);
    bn_apply64<<<(M * D2 + 255) / 256, 256>>>(0, 1, 0, g1, b1, M);
    // 3. Hbig = h @ Wbig   [M,64]@[64,960]
    gemm_kernel<<<gemmGridH, 256>>>(nullptr, 1, nullptr, 6, /*C=*/2, M, D2, KPTS * D2);
    // 4. edge scatter into g_y
    edge_kernel<<<(E + 7) / 8, 256>>>(pos, e_ref, e_qry, kp, E);
    // 5. stats(y) ; ybn = leaky(bn(y)) -> g_h (reuse)
    stats_kernel<64><<<240, 256>>>(3, M, 128);
    bn_apply64<<<(M * D2 + 255) / 256, 256>>>(3, 1, 128, gkp, bkp, M);
    // 6. u2 = ybn @ W2   [M,64]@[64,256]
    gemm_kernel<<<gemmGrid4, 256>>>(nullptr, 1, W2, -1, /*C=*/4, M, D2, DOUT);
    stats_kernel<256><<<240, 256>>>(4, M, 256);
    // 7. usc = x @ Wsc   [M,128]@[128,256]
    gemm_kernel<<<gemmGrid4, 256>>>(x, -1, Wsc, -1, /*C=*/5, M, DIN, DOUT);
    stats_kernel<256><<<240, 256>>>(5, M, 768);
    // 8. out = leaky(bn(u2)) + bn(usc)
    final_kernel<<<(M * DOUT + 255) / 256, 256>>>(out, g2, b2, gsc, bsc, M);
}